// round 9
// baseline (speedup 1.0000x reference)
#include <cuda_runtime.h>
#include <math.h>

// Problem constants
#define BB 8
#define LL 2048
#define DD 1024
#define ND3 3072
#define KS 32
#define JJ 512
#define T0V 2050
#define TSV 514
#define T1V 2082
#define SCALE 0.03125f

// padded score pitches (multiple of 4 floats -> 16B-aligned rows)
#define SP0 2052
#define SP1 2084

#define OUT0_ROWS 2016
#define OUT1_ROWS 2048
#define OFF1 ((long long)BB * OUT0_ROWS * DD)

// ------------------- scratch -------------------
__device__ float g_X[BB * T1V * DD];
__device__ float g_QKV[BB * T1V * ND3];      // fused Q|K|V (pitch 3072); also used as KV (pitch 2048) in summarize
__device__ float g_O[BB * T1V * DD];
__device__ float g_H[BB * T1V * DD];
__device__ float g_S[(long long)BB * T1V * SP1];
__device__ float g_Wpack[DD * ND3];          // tf32-rounded [k][q|k|v]
__device__ float g_Wo_r[DD * DD];            // tf32-rounded Wo
__device__ float g_bpack[ND3];               // bq|bk|bv
__device__ float g_M1[BB * DD];
__device__ float g_S1[BB * DD];
__device__ float g_Qn[BB * DD];
__device__ float g_Kp[BB * DD];
__device__ float g_P1[BB * DD];
__device__ float g_TA[BB * DD];
__device__ float g_TB[BB * DD];

// ------------------- helpers -------------------
__device__ __forceinline__ unsigned f2tf(float x) {
    unsigned r;
    asm("cvt.rna.tf32.f32 %0, %1;" : "=r"(r) : "f"(x));
    return r;
}
__device__ __forceinline__ float roundtf(float x) { return __uint_as_float(f2tf(x)); }

__device__ __forceinline__ void mma_tf32(float (&c)[4], unsigned a0, unsigned a1,
                                         unsigned a2, unsigned a3, unsigned b0, unsigned b1) {
    asm volatile(
        "mma.sync.aligned.m16n8k8.row.col.f32.tf32.tf32.f32 "
        "{%0,%1,%2,%3}, {%4,%5,%6,%7}, {%8,%9}, {%0,%1,%2,%3};"
        : "+f"(c[0]), "+f"(c[1]), "+f"(c[2]), "+f"(c[3])
        : "r"(a0), "r"(a1), "r"(a2), "r"(a3), "r"(b0), "r"(b1));
}

__device__ __forceinline__ void cp_async16(float* s, const float* g, int bytes) {
    unsigned saddr = (unsigned)__cvta_generic_to_shared(s);
    asm volatile("cp.async.cg.shared.global [%0], [%1], 16, %2;\n"
                 :: "r"(saddr), "l"(g), "r"(bytes));
}

// ------------------- TF32 tensor-core GEMM -------------------
// C = alpha * A @ op(B) + bias.  A: MxK row-major (pitch lda).
// TRANSB=false: B is KxN (pitch ldb).  TRANSB=true: B is NxK (pitch ldb), C = A@B^T.
// Block tile 128x256, k-tile 32, 8 warps (2x4), warp tile 64x64,
// mma.sync.m16n8k8.tf32, cp.async double-buffered.
// CONV: convert operands to tf32 in the inner loop; else operands must be pre-rounded.
// All pitches/base pointers must be 16B aligned (pitch multiple of 4 floats).
#define APITCH 36
#define BPITCH_NN 264
#define AS_FLOATS (128 * APITCH)          // 4608
#define BS_FLOATS (256 * APITCH)          // 9216 (NN needs 32*264=8448 <= this)
#define STAGE_FLOATS (AS_FLOATS + BS_FLOATS)
#define GEMM_SMEM_BYTES (2 * STAGE_FLOATS * 4)   // 110592

template <bool TRANSB, bool CONV>
__global__ __launch_bounds__(256, 1) void gemm_tf32_kernel(
    const float* __restrict__ A, const float* __restrict__ Bm,
    const float* __restrict__ bias, float* __restrict__ C,
    int M, int N, int Kd, float alpha,
    int lda, int ldb, int ldc,
    long long sA, long long sB, long long sC, int roundOut)
{
    A += (long long)blockIdx.z * sA;
    Bm += (long long)blockIdx.z * sB;
    C += (long long)blockIdx.z * sC;

    extern __shared__ float smem[];
    const int tid = threadIdx.x;
    const int warp = tid >> 5;
    const int lane = tid & 31;
    const int warp_m = warp & 1;   // 2 warps in M (64 each)
    const int warp_n = warp >> 1;  // 4 warps in N (64 each)
    const int qrow = lane >> 2;
    const int qcol = lane & 3;
    const int m0 = blockIdx.y * 128;
    const int n0 = blockIdx.x * 256;

    float acc[32][4];
#pragma unroll
    for (int i = 0; i < 32; i++)
#pragma unroll
        for (int j = 0; j < 4; j++) acc[i][j] = 0.f;

    const int nk = (Kd + 31) >> 5;

    auto load_tiles = [&](int kt, int buf) {
        float* As = smem + buf * STAGE_FLOATS;
        float* Bs = As + AS_FLOATS;
        int k0 = kt << 5;
        // A tile: 128 rows x 32 k
#pragma unroll
        for (int c = 0; c < 4; c++) {
            int idx = c * 256 + tid;
            int m = idx >> 3, k4 = (idx & 7) << 2;
            int gm = m0 + m, gk = k0 + k4;
            int rem = Kd - gk;
            int bytes = (gm < M) ? (rem >= 4 ? 16 : (rem > 0 ? rem * 4 : 0)) : 0;
            const float* src = bytes ? (A + (long long)gm * lda + gk) : A;
            cp_async16(As + m * APITCH + k4, src, bytes);
        }
        if (!TRANSB) {
            // B tile: 32 k-rows x 256 n
#pragma unroll
            for (int c = 0; c < 8; c++) {
                int idx = c * 256 + tid;
                int k = idx >> 6, n4 = (idx & 63) << 2;
                int gk = k0 + k, gn = n0 + n4;
                int rem = N - gn;
                int bytes = (gk < Kd) ? (rem >= 4 ? 16 : (rem > 0 ? rem * 4 : 0)) : 0;
                const float* src = bytes ? (Bm + (long long)gk * ldb + gn) : Bm;
                cp_async16(Bs + k * BPITCH_NN + n4, src, bytes);
            }
        } else {
            // B tile: 256 n-rows x 32 k
#pragma unroll
            for (int c = 0; c < 8; c++) {
                int idx = c * 256 + tid;
                int n = idx >> 3, k4 = (idx & 7) << 2;
                int gn = n0 + n, gk = k0 + k4;
                int rem = Kd - gk;
                int bytes = (gn < N) ? (rem >= 4 ? 16 : (rem > 0 ? rem * 4 : 0)) : 0;
                const float* src = bytes ? (Bm + (long long)gn * ldb + gk) : Bm;
                cp_async16(Bs + n * APITCH + k4, src, bytes);
            }
        }
        asm volatile("cp.async.commit_group;\n");
    };

    load_tiles(0, 0);

    for (int kt = 0; kt < nk; kt++) {
        if (kt + 1 < nk) {
            load_tiles(kt + 1, (kt + 1) & 1);
            asm volatile("cp.async.wait_group 1;\n");
        } else {
            asm volatile("cp.async.wait_group 0;\n");
        }
        __syncthreads();

        const float* As = smem + (kt & 1) * STAGE_FLOATS;
        const float* Bs = As + AS_FLOATS;
        const unsigned* Asu = (const unsigned*)As;
        const unsigned* Bsu = (const unsigned*)Bs;
        const int abase0 = (warp_m * 64 + qrow) * APITCH + qcol;

#pragma unroll
        for (int kk = 0; kk < 32; kk += 8) {
            unsigned af[4][4], bf[8][2];
#pragma unroll
            for (int mt = 0; mt < 4; mt++) {
                int base = abase0 + mt * 16 * APITCH + kk;
                if (CONV) {
                    af[mt][0] = f2tf(As[base]);
                    af[mt][1] = f2tf(As[base + 8 * APITCH]);
                    af[mt][2] = f2tf(As[base + 4]);
                    af[mt][3] = f2tf(As[base + 8 * APITCH + 4]);
                } else {
                    af[mt][0] = Asu[base];
                    af[mt][1] = Asu[base + 8 * APITCH];
                    af[mt][2] = Asu[base + 4];
                    af[mt][3] = Asu[base + 8 * APITCH + 4];
                }
            }
#pragma unroll
            for (int nt = 0; nt < 8; nt++) {
                int n = warp_n * 64 + nt * 8 + qrow;
                if (!TRANSB) {
                    int base = (kk + qcol) * BPITCH_NN + n;
                    if (CONV) {
                        bf[nt][0] = f2tf(Bs[base]);
                        bf[nt][1] = f2tf(Bs[base + 4 * BPITCH_NN]);
                    } else {
                        bf[nt][0] = Bsu[base];
                        bf[nt][1] = Bsu[base + 4 * BPITCH_NN];
                    }
                } else {
                    int base = n * APITCH + kk + qcol;
                    if (CONV) {
                        bf[nt][0] = f2tf(Bs[base]);
                        bf[nt][1] = f2tf(Bs[base + 4]);
                    } else {
                        bf[nt][0] = Bsu[base];
                        bf[nt][1] = Bsu[base + 4];
                    }
                }
            }
#pragma unroll
            for (int mt = 0; mt < 4; mt++)
#pragma unroll
                for (int nt = 0; nt < 8; nt++)
                    mma_tf32(acc[mt * 8 + nt], af[mt][0], af[mt][1], af[mt][2], af[mt][3],
                             bf[nt][0], bf[nt][1]);
        }
        __syncthreads();
    }

#pragma unroll
    for (int mt = 0; mt < 4; mt++) {
#pragma unroll
        for (int nt = 0; nt < 8; nt++) {
            float* c = acc[mt * 8 + nt];
            int gm = m0 + warp_m * 64 + mt * 16 + qrow;
            int gn = n0 + warp_n * 64 + nt * 8 + (qcol << 1);
            float bx = 0.f, by = 0.f;
            if (bias && gn < N) { bx = bias[gn]; by = bias[gn + 1]; }
            if (gm < M && gn < N) {
                float x = alpha * c[0] + bx, y = alpha * c[1] + by;
                if (roundOut) { x = roundtf(x); y = roundtf(y); }
                *(float2*)(C + (long long)gm * ldc + gn) = make_float2(x, y);
            }
            if (gm + 8 < M && gn < N) {
                float x = alpha * c[2] + bx, y = alpha * c[3] + by;
                if (roundOut) { x = roundtf(x); y = roundtf(y); }
                *(float2*)(C + (long long)(gm + 8) * ldc + gn) = make_float2(x, y);
            }
        }
    }
}

// ------------------- row softmax (pitched, tf32-rounded output) -------------------
__global__ __launch_bounds__(256) void softmax_rows_kernel(float* __restrict__ S, int Tk, int pitch)
{
    long long row = blockIdx.x;
    float* r = S + row * (long long)pitch;
    int tid = threadIdx.x;
    __shared__ float red[256];

    float v[9];
    int cnt = 0;
    float mx = -1e30f;
    for (int i = tid; i < Tk; i += 256) {
        v[cnt] = r[i];
        mx = fmaxf(mx, v[cnt]);
        cnt++;
    }
    red[tid] = mx;
    __syncthreads();
    for (int s = 128; s > 0; s >>= 1) {
        if (tid < s) red[tid] = fmaxf(red[tid], red[tid + s]);
        __syncthreads();
    }
    mx = red[0];
    __syncthreads();

    float sum = 0.f;
    for (int c = 0; c < cnt; c++) {
        v[c] = __expf(v[c] - mx);
        sum += v[c];
    }
    red[tid] = sum;
    __syncthreads();
    for (int s = 128; s > 0; s >>= 1) {
        if (tid < s) red[tid] += red[tid + s];
        __syncthreads();
    }
    float inv = 1.f / red[0];

    cnt = 0;
    for (int i = tid; i < Tk; i += 256) r[i] = roundtf(v[cnt++] * inv);
}

// ------------------- round + pack weights -------------------
__global__ void round_weights_kernel(const float* __restrict__ Wq, const float* __restrict__ Wk,
                                     const float* __restrict__ Wv, const float* __restrict__ Wo,
                                     const float* __restrict__ bq, const float* __restrict__ bk,
                                     const float* __restrict__ bv,
                                     float* __restrict__ pack, float* __restrict__ wo_r,
                                     float* __restrict__ bpack)
{
    int idx = blockIdx.x * blockDim.x + threadIdx.x;
    if (idx >= DD * DD) return;
    int k = idx >> 10, n = idx & (DD - 1);
    pack[k * ND3 + n] = roundtf(Wq[idx]);
    pack[k * ND3 + DD + n] = roundtf(Wk[idx]);
    pack[k * ND3 + 2 * DD + n] = roundtf(Wv[idx]);
    wo_r[idx] = roundtf(Wo[idx]);
    if (idx < DD) {
        bpack[idx] = bq[idx];
        bpack[DD + idx] = bk[idx];
        bpack[2 * DD + idx] = bv[idx];
    }
}

// ------------------- build inputs (tf32-rounded) -------------------
__global__ void build_x0_kernel(float* __restrict__ X, const float* __restrict__ seg0)
{
    long long idx = (long long)blockIdx.x * blockDim.x + threadIdx.x;
    if (idx >= (long long)BB * T0V * DD) return;
    int d = (int)(idx & (DD - 1));
    long long r = idx >> 10;
    int t = (int)(r % T0V);
    int b = (int)(r / T0V);
    float v = 0.f;
    if (t >= 1 && t <= LL) v = seg0[((long long)b * LL + (t - 1)) * DD + d];
    X[idx] = roundtf(v);
}

__global__ void build_xs_kernel(float* __restrict__ X, const float* __restrict__ seg1,
                                const float* __restrict__ prompt)
{
    long long idx = (long long)blockIdx.x * blockDim.x + threadIdx.x;
    if (idx >= (long long)BB * TSV * DD) return;
    int d = (int)(idx & (DD - 1));
    long long r = idx >> 10;
    int t = (int)(r % TSV);
    int b = (int)(r / TSV);
    float v;
    if (t == 0 || t == TSV - 1) v = prompt[d];
    else v = seg1[((long long)b * LL + (t - 1)) * DD + d];
    X[idx] = roundtf(v);
}

__global__ void build_x1_kernel(float* __restrict__ X, const float* __restrict__ seg0,
                                const float* __restrict__ seg1, const float* __restrict__ P1)
{
    long long idx = (long long)blockIdx.x * blockDim.x + threadIdx.x;
    if (idx >= (long long)BB * T1V * DD) return;
    int d = (int)(idx & (DD - 1));
    long long r = idx >> 10;
    int t = (int)(r % T1V);
    int b = (int)(r / T1V);
    float v;
    if (t < KS) v = seg0[((long long)b * LL + (LL - KS + t)) * DD + d];
    else if (t == KS || t == T1V - 1) v = P1[b * DD + d];
    else v = seg1[((long long)b * LL + (t - KS - 1)) * DD + d];
    X[idx] = roundtf(v);
}

__global__ void gather_q_kernel(float* __restrict__ dst, const float* __restrict__ seg1)
{
    int idx = blockIdx.x * blockDim.x + threadIdx.x;
    if (idx >= BB * DD) return;
    int d = idx & (DD - 1);
    int b = idx >> 10;
    dst[idx] = roundtf(seg1[((long long)b * LL + (JJ - 1)) * DD + d]);
}

__global__ void copy_rows_kernel(float* __restrict__ dst, const float* __restrict__ H,
                                 int T, int t_begin, int rows)
{
    long long idx = (long long)blockIdx.x * blockDim.x + threadIdx.x;
    if (idx >= (long long)BB * rows * DD) return;
    int d = (int)(idx & (DD - 1));
    long long r = idx >> 10;
    int t = (int)(r % rows);
    int b = (int)(r / rows);
    dst[idx] = H[((long long)b * T + t_begin + t) * DD + d];
}

// ------------------- summarize attention (KV packed, pitch 2048) -------------------
__global__ __launch_bounds__(256) void summ_attn_kernel(
    const float* __restrict__ Qrow, const float* __restrict__ KV,
    float* __restrict__ out, int T)
{
    int b = blockIdx.x;
    const float* q = Qrow + b * DD;
    const float* Kb = KV + (long long)b * T * 2048;      // row j: Kb + j*2048
    int tid = threadIdx.x;
    int lane = tid & 31, warp = tid >> 5;
    __shared__ float sc[TSV];
    __shared__ float red[256];

    for (int j = warp; j < T; j += 8) {
        float s = 0.f;
        const float* kr = Kb + (long long)j * 2048;
        for (int d = lane; d < DD; d += 32) s += q[d] * kr[d];
        for (int o = 16; o > 0; o >>= 1) s += __shfl_xor_sync(0xFFFFFFFFu, s, o);
        if (lane == 0) sc[j] = s * SCALE;
    }
    __syncthreads();

    float mx = -1e30f;
    for (int i = tid; i < T; i += 256) mx = fmaxf(mx, sc[i]);
    red[tid] = mx;
    __syncthreads();
    for (int s = 128; s > 0; s >>= 1) {
        if (tid < s) red[tid] = fmaxf(red[tid], red[tid + s]);
        __syncthreads();
    }
    mx = red[0];
    __syncthreads();

    float sum = 0.f;
    for (int i = tid; i < T; i += 256) {
        float e = __expf(sc[i] - mx);
        sc[i] = e;
        sum += e;
    }
    red[tid] = sum;
    __syncthreads();
    for (int s = 128; s > 0; s >>= 1) {
        if (tid < s) red[tid] += red[tid + s];
        __syncthreads();
    }
    float inv = 1.f / red[0];
    __syncthreads();
    for (int i = tid; i < T; i += 256) sc[i] *= inv;
    __syncthreads();

    const float* Vb = Kb + DD;
    for (int d = tid; d < DD; d += 256) {
        float acc = 0.f;
        for (int j = 0; j < T; j++) acc = fmaf(sc[j], Vb[(long long)j * 2048 + d], acc);
        out[b * DD + d] = acc;
    }
}

// ------------------- memory attention -------------------
__global__ __launch_bounds__(256) void mem_attn_kernel(
    const float* __restrict__ Qn, const float* __restrict__ Kp,
    const float* __restrict__ M1, float* __restrict__ P1)
{
    __shared__ float sc[BB][BB];
    int tid = threadIdx.x;
    int lane = tid & 31, warp = tid >> 5;

    for (int j = 0; j < BB; j++) {
        float s = 0.f;
        for (int d = lane; d < DD; d += 32) s += Qn[warp * DD + d] * Kp[j * DD + d];
        for (int o = 16; o > 0; o >>= 1) s += __shfl_xor_sync(0xFFFFFFFFu, s, o);
        if (lane == 0) sc[warp][j] = s * SCALE;
    }
    __syncthreads();

    if (tid < BB) {
        float mx = -1e30f;
        for (int j = 0; j < BB; j++) mx = fmaxf(mx, sc[tid][j]);
        float sum = 0.f;
        for (int j = 0; j < BB; j++) {
            float e = __expf(sc[tid][j] - mx);
            sc[tid][j] = e;
            sum += e;
        }
        float inv = 1.f / sum;
        for (int j = 0; j < BB; j++) sc[tid][j] *= inv;
    }
    __syncthreads();

    for (int idx = tid; idx < BB * DD; idx += 256) {
        int b = idx >> 10, d = idx & (DD - 1);
        float acc = 0.f;
        for (int j = 0; j < BB; j++) acc = fmaf(sc[b][j], M1[j * DD + d], acc);
        P1[idx] = acc;
    }
}

// ------------------- host orchestration -------------------
static inline void gemm(const float* A, const float* Bm, const float* bias, float* C,
                        int M, int N, int Kd, float alpha, int batch,
                        long long sA, long long sB, long long sC, bool transB,
                        int lda, int ldb, int ldc, bool conv, int roundOut)
{
    dim3 grid((N + 255) / 256, (M + 127) / 128, batch);
    if (transB) {
        if (conv) {
            cudaFuncSetAttribute(gemm_tf32_kernel<true, true>,
                                 cudaFuncAttributeMaxDynamicSharedMemorySize, GEMM_SMEM_BYTES);
            gemm_tf32_kernel<true, true><<<grid, 256, GEMM_SMEM_BYTES>>>(
                A, Bm, bias, C, M, N, Kd, alpha, lda, ldb, ldc, sA, sB, sC, roundOut);
        } else {
            cudaFuncSetAttribute(gemm_tf32_kernel<true, false>,
                                 cudaFuncAttributeMaxDynamicSharedMemorySize, GEMM_SMEM_BYTES);
            gemm_tf32_kernel<true, false><<<grid, 256, GEMM_SMEM_BYTES>>>(
                A, Bm, bias, C, M, N, Kd, alpha, lda, ldb, ldc, sA, sB, sC, roundOut);
        }
    } else {
        if (conv) {
            cudaFuncSetAttribute(gemm_tf32_kernel<false, true>,
                                 cudaFuncAttributeMaxDynamicSharedMemorySize, GEMM_SMEM_BYTES);
            gemm_tf32_kernel<false, true><<<grid, 256, GEMM_SMEM_BYTES>>>(
                A, Bm, bias, C, M, N, Kd, alpha, lda, ldb, ldc, sA, sB, sC, roundOut);
        } else {
            cudaFuncSetAttribute(gemm_tf32_kernel<false, false>,
                                 cudaFuncAttributeMaxDynamicSharedMemorySize, GEMM_SMEM_BYTES);
            gemm_tf32_kernel<false, false><<<grid, 256, GEMM_SMEM_BYTES>>>(
                A, Bm, bias, C, M, N, Kd, alpha, lda, ldb, ldc, sA, sB, sC, roundOut);
        }
    }
}

extern "C" void kernel_launch(void* const* d_in, const int* in_sizes, int n_in,
                              void* d_out, int out_size)
{
    const float* seg0   = (const float*)d_in[0];
    const float* seg1   = (const float*)d_in[1];
    const float* prompt = (const float*)d_in[2];
    const float* Wq_mem = (const float*)d_in[3];
    const float* bq_mem = (const float*)d_in[4];
    const float* Wk_mem = (const float*)d_in[5];
    const float* bk_mem = (const float*)d_in[6];
    const float* Wq     = (const float*)d_in[7];
    const float* bq     = (const float*)d_in[8];
    const float* Wk     = (const float*)d_in[9];
    const float* bk     = (const float*)d_in[10];
    const float* Wv     = (const float*)d_in[11];
    const float* bv     = (const float*)d_in[12];
    const float* Wo     = (const float*)d_in[13];
    const float* bo     = (const float*)d_in[14];
    float* out = (float*)d_out;

    float *pX, *pQKV, *pO, *pH, *pS, *pWp, *pWo, *pbp;
    float *pM1, *pS1, *pQn, *pKp, *pP1, *pTA, *pTB;
    cudaGetSymbolAddress((void**)&pX, g_X);
    cudaGetSymbolAddress((void**)&pQKV, g_QKV);
    cudaGetSymbolAddress((void**)&pO, g_O);
    cudaGetSymbolAddress((void**)&pH, g_H);
    cudaGetSymbolAddress((void**)&pS, g_S);
    cudaGetSymbolAddress((void**)&pWp, g_Wpack);
    cudaGetSymbolAddress((void**)&pWo, g_Wo_r);
    cudaGetSymbolAddress((void**)&pbp, g_bpack);
    cudaGetSymbolAddress((void**)&pM1, g_M1);
    cudaGetSymbolAddress((void**)&pS1, g_S1);
    cudaGetSymbolAddress((void**)&pQn, g_Qn);
    cudaGetSymbolAddress((void**)&pKp, g_Kp);
    cudaGetSymbolAddress((void**)&pP1, g_P1);
    cudaGetSymbolAddress((void**)&pTA, g_TA);
    cudaGetSymbolAddress((void**)&pTB, g_TB);

    const int nthr = 256;

    round_weights_kernel<<<(DD * DD + nthr - 1) / nthr, nthr>>>(
        Wq, Wk, Wv, Wo, bq, bk, bv, pWp, pWo, pbp);

    // ---------------- Phase 0: backbone over [0, seg0, 0], T = 2050 ----------------
    {
        long long n = (long long)BB * T0V * DD;
        build_x0_kernel<<<(int)((n + nthr - 1) / nthr), nthr>>>(pX, seg0);

        int M = BB * T0V;
        // fused QKV projection: C (M x 3072), pitch 3072, pre-rounded output
        gemm(pX, pWp, pbp, pQKV, M, ND3, DD, 1.f, 1, 0, 0, 0, false, DD, ND3, ND3, false, 1);
        const float* Qv = pQKV;            // pitch 3072
        const float* Kv = pQKV + DD;
        const float* Vv = pQKV + 2 * DD;

        gemm(Qv, Kv, nullptr, pS, T0V, T0V, DD, SCALE, BB,
             (long long)T0V * ND3, (long long)T0V * ND3, (long long)T0V * SP0, true,
             ND3, ND3, SP0, false, 0);
        softmax_rows_kernel<<<BB * T0V, 256>>>(pS, T0V, SP0);
        gemm(pS, Vv, nullptr, pO, T0V, DD, T0V, 1.f, BB,
             (long long)T0V * SP0, (long long)T0V * ND3, (long long)T0V * DD, false,
             SP0, ND3, DD, false, 1);
        gemm(pO, pWo, bo, pH, M, DD, DD, 1.f, 1, 0, 0, 0, false, DD, DD, DD, false, 0);

        long long n0 = (long long)BB * OUT0_ROWS * DD;
        copy_rows_kernel<<<(int)((n0 + nthr - 1) / nthr), nthr>>>(out, pH, T0V, KS + 1, OUT0_ROWS);
        copy_rows_kernel<<<(BB * DD + nthr - 1) / nthr, nthr>>>(pM1, pH, T0V, T0V - 1, 1);
    }

    // ---------------- Summarize(seg1): T = 514 ----------------
    {
        long long n = (long long)BB * TSV * DD;
        build_xs_kernel<<<(int)((n + nthr - 1) / nthr), nthr>>>(pX, seg1, prompt);

        int M = BB * TSV;
        // fused K|V projection (N=2048), pitch 2048
        gemm(pX, pWp + DD, pbp + DD, pQKV, M, 2 * DD, DD, 1.f, 1, 0, 0, 0, false,
             DD, ND3, 2 * DD, false, 0);

        gather_q_kernel<<<(BB * DD + nthr - 1) / nthr, nthr>>>(pTA, seg1);
        gemm(pTA, pWp, bq, pTB, BB, DD, DD, 1.f, 1, 0, 0, 0, false, DD, ND3, DD, false, 0);

        summ_attn_kernel<<<BB, 256>>>(pTB, pQKV, pTA, TSV);
        gemm(pTA, Wo, bo, pS1, BB, DD, DD, 1.f, 1, 0, 0, 0, false, DD, DD, DD, true, 0);
    }

    // ---------------- Memory attention ----------------
    {
        gemm(pS1, Wq_mem, bq_mem, pQn, BB, DD, DD, 1.f, 1, 0, 0, 0, false, DD, DD, DD, true, 0);
        gemm(pM1, Wk_mem, bk_mem, pKp, BB, DD, DD, 1.f, 1, 0, 0, 0, false, DD, DD, DD, true, 0);
        mem_attn_kernel<<<1, 256>>>(pQn, pKp, pM1, pP1);
    }

    // ---------------- Phase 1: backbone over [sensory, P1, seg1, P1], T = 2082 ----------------
    {
        long long n = (long long)BB * T1V * DD;
        build_x1_kernel<<<(int)((n + nthr - 1) / nthr), nthr>>>(pX, seg0, seg1, pP1);

        int M = BB * T1V;
        gemm(pX, pWp, pbp, pQKV, M, ND3, DD, 1.f, 1, 0, 0, 0, false, DD, ND3, ND3, false, 1);
        const float* Qv = pQKV;
        const float* Kv = pQKV + DD;
        const float* Vv = pQKV + 2 * DD;

        gemm(Qv, Kv, nullptr, pS, T1V, T1V, DD, SCALE, BB,
             (long long)T1V * ND3, (long long)T1V * ND3, (long long)T1V * SP1, true,
             ND3, ND3, SP1, false, 0);
        softmax_rows_kernel<<<BB * T1V, 256>>>(pS, T1V, SP1);
        gemm(pS, Vv, nullptr, pO, T1V, DD, T1V, 1.f, BB,
             (long long)T1V * SP1, (long long)T1V * ND3, (long long)T1V * DD, false,
             SP1, ND3, DD, false, 1);
        gemm(pO, pWo, bo, pH, M, DD, DD, 1.f, 1, 0, 0, 0, false, DD, DD, DD, false, 0);

        long long n1 = (long long)BB * OUT1_ROWS * DD;
        copy_rows_kernel<<<(int)((n1 + nthr - 1) / nthr), nthr>>>(out + OFF1, pH, T1V, KS + 1, OUT1_ROWS);
    }
}

// round 10
// speedup vs baseline: 1.8105x; 1.8105x over previous
#include <cuda_runtime.h>
#include <cuda_fp16.h>
#include <math.h>

// Problem constants
#define BB 8
#define LL 2048
#define DD 1024
#define ND3 3072
#define KS 32
#define JJ 512
#define T0V 2050
#define TSV 514
#define T1V 2082
#define SCALE 0.03125f

// fp32 score pitches (multiple of 4 floats)
#define SP0 2052
#define SP1 2084
// half prob pitches (multiple of 8 halfs -> 16B rows)
#define SPH0 2056
#define SPH1 2088

#define OUT0_ROWS 2016
#define OUT1_ROWS 2048
#define OFF1 ((long long)BB * OUT0_ROWS * DD)

// ------------------- scratch -------------------
__device__ __half g_Xh[BB * T1V * DD];
__device__ __half g_QKVh[BB * T1V * ND3];   // fused Q|K|V pitch 3072; K|V pitch 2048 in summarize
__device__ __half g_Ph[(long long)BB * T1V * SPH1];  // softmax probs (half)
__device__ __half g_Oh[BB * T1V * DD];
__device__ float  g_S[(long long)BB * T1V * SP1];    // fp32 scores
__device__ float  g_H[BB * T1V * DD];
__device__ __half g_Wpack[DD * ND3];        // fp16 [k][q|k|v]
__device__ __half g_Wo_h[DD * DD];
__device__ __half g_Wqm_h[DD * DD];
__device__ __half g_Wkm_h[DD * DD];
__device__ float  g_bpack[ND3];
__device__ float  g_M1[BB * DD];
__device__ __half g_M1h[BB * DD];
__device__ __half g_S1h[BB * DD];
__device__ float  g_Qn[BB * DD];
__device__ float  g_Kp[BB * DD];
__device__ float  g_P1[BB * DD];
__device__ __half g_TAh[BB * DD];
__device__ __half g_TBh[BB * DD];

// ------------------- helpers -------------------
__device__ __forceinline__ __half f2h(float x) { return __float2half_rn(x); }

__device__ __forceinline__ void mma_f16(float (&c)[4], unsigned a0, unsigned a1,
                                        unsigned a2, unsigned a3, unsigned b0, unsigned b1) {
    asm volatile(
        "mma.sync.aligned.m16n8k16.row.col.f32.f16.f16.f32 "
        "{%0,%1,%2,%3}, {%4,%5,%6,%7}, {%8,%9}, {%0,%1,%2,%3};"
        : "+f"(c[0]), "+f"(c[1]), "+f"(c[2]), "+f"(c[3])
        : "r"(a0), "r"(a1), "r"(a2), "r"(a3), "r"(b0), "r"(b1));
}

__device__ __forceinline__ void ldsm4(unsigned& r0, unsigned& r1, unsigned& r2, unsigned& r3,
                                      unsigned addr) {
    asm volatile("ldmatrix.sync.aligned.m8n8.x4.shared.b16 {%0,%1,%2,%3}, [%4];"
                 : "=r"(r0), "=r"(r1), "=r"(r2), "=r"(r3) : "r"(addr));
}
__device__ __forceinline__ void ldsm2(unsigned& r0, unsigned& r1, unsigned addr) {
    asm volatile("ldmatrix.sync.aligned.m8n8.x2.shared.b16 {%0,%1}, [%2];"
                 : "=r"(r0), "=r"(r1) : "r"(addr));
}
__device__ __forceinline__ void ldsm2t(unsigned& r0, unsigned& r1, unsigned addr) {
    asm volatile("ldmatrix.sync.aligned.m8n8.x2.trans.shared.b16 {%0,%1}, [%2];"
                 : "=r"(r0), "=r"(r1) : "r"(addr));
}

__device__ __forceinline__ void cp_async16(__half* s, const __half* g, int bytes) {
    unsigned saddr = (unsigned)__cvta_generic_to_shared(s);
    asm volatile("cp.async.cg.shared.global [%0], [%1], 16, %2;\n"
                 :: "r"(saddr), "l"(g), "r"(bytes));
}

// ------------------- FP16 tensor-core GEMM -------------------
// C = alpha * A @ op(B) + bias.  A: MxK half row-major (pitch lda halfs).
// TRANSB=false: B KxN (pitch ldb).  TRANSB=true: B NxK, C=A@B^T.
// OUTHALF: C is half (pitch ldc halfs); else fp32 (pitch ldc floats).
// Block 128x128, ktile 32, 8 warps (2x4), warp tile 64x32, mma.m16n8k16,
// ldmatrix fragments, cp.async double-buffered. Pitches must give 16B rows.
#define APH 40            // A / B-NT smem pitch (halfs); row stride 80B
#define BPH_NN 136        // B-NN smem pitch (halfs); row stride 272B
#define AS_HALFS (128 * APH)              // 5120
#define BS_HALFS (128 * APH)              // >= 32*136
#define STAGE_HALFS (AS_HALFS + BS_HALFS)
#define GEMM_SMEM_BYTES (2 * STAGE_HALFS * 2)   // 40960

template <bool TRANSB, bool OUTHALF>
__global__ __launch_bounds__(256, 2) void gemm_fp16_kernel(
    const __half* __restrict__ A, const __half* __restrict__ Bm,
    const float* __restrict__ bias, void* __restrict__ Cv,
    int M, int N, int Kd, float alpha,
    int lda, int ldb, int ldc,
    long long sA, long long sB, long long sC)
{
    A += (long long)blockIdx.z * sA;
    Bm += (long long)blockIdx.z * sB;

    extern __shared__ __half smem[];
    const int tid = threadIdx.x;
    const int warp = tid >> 5;
    const int lane = tid & 31;
    const int warp_m = warp & 1;   // 2 warps in M
    const int warp_n = warp >> 1;  // 4 warps in N
    const int qrow = lane >> 2;
    const int qcol = lane & 3;
    const int m0 = blockIdx.y * 128;
    const int n0 = blockIdx.x * 128;

    float acc[16][4];
#pragma unroll
    for (int i = 0; i < 16; i++)
#pragma unroll
        for (int j = 0; j < 4; j++) acc[i][j] = 0.f;

    const int nk = (Kd + 31) >> 5;

    auto load_tiles = [&](int kt, int buf) {
        __half* As = smem + buf * STAGE_HALFS;
        __half* Bs = As + AS_HALFS;
        int k0 = kt << 5;
        // A tile: 128 rows x 32 halfs (4x16B per row), 512 chunks
#pragma unroll
        for (int c = 0; c < 2; c++) {
            int idx = c * 256 + tid;
            int m = idx >> 2, k8 = (idx & 3) << 3;
            int gm = m0 + m, gk = k0 + k8;
            int rem = Kd - gk;
            int bytes = (gm < M) ? (rem >= 8 ? 16 : (rem > 0 ? rem * 2 : 0)) : 0;
            const __half* src = bytes ? (A + (long long)gm * lda + gk) : A;
            cp_async16(As + m * APH + k8, src, bytes);
        }
        if (!TRANSB) {
            // B tile: 32 k-rows x 128 halfs (16x16B per row), 512 chunks
#pragma unroll
            for (int c = 0; c < 2; c++) {
                int idx = c * 256 + tid;
                int k = idx >> 4, n8 = (idx & 15) << 3;
                int gk = k0 + k, gn = n0 + n8;
                int rem = N - gn;
                int bytes = (gk < Kd) ? (rem >= 8 ? 16 : (rem > 0 ? rem * 2 : 0)) : 0;
                const __half* src = bytes ? (Bm + (long long)gk * ldb + gn) : Bm;
                cp_async16(Bs + k * BPH_NN + n8, src, bytes);
            }
        } else {
            // B tile: 128 n-rows x 32 halfs
#pragma unroll
            for (int c = 0; c < 2; c++) {
                int idx = c * 256 + tid;
                int n = idx >> 2, k8 = (idx & 3) << 3;
                int gn = n0 + n, gk = k0 + k8;
                int rem = Kd - gk;
                int bytes = (gn < N) ? (rem >= 8 ? 16 : (rem > 0 ? rem * 2 : 0)) : 0;
                const __half* src = bytes ? (Bm + (long long)gn * ldb + gk) : Bm;
                cp_async16(Bs + n * APH + k8, src, bytes);
            }
        }
        asm volatile("cp.async.commit_group;\n");
    };

    load_tiles(0, 0);

    // precomputed ldmatrix address components (bytes)
    const int a_off = (warp_m * 64 + (lane & 15)) * (APH * 2) + (lane >> 4) * 16;
    const int bnt_off = (warp_n * 32 + (lane & 7)) * (APH * 2) + ((lane >> 3) & 1) * 16;

    for (int kt = 0; kt < nk; kt++) {
        if (kt + 1 < nk) {
            load_tiles(kt + 1, (kt + 1) & 1);
            asm volatile("cp.async.wait_group 1;\n");
        } else {
            asm volatile("cp.async.wait_group 0;\n");
        }
        __syncthreads();

        const __half* As = smem + (kt & 1) * STAGE_HALFS;
        const __half* Bs = As + AS_HALFS;
        unsigned as_base = (unsigned)__cvta_generic_to_shared(As);
        unsigned bs_base = (unsigned)__cvta_generic_to_shared(Bs);

#pragma unroll
        for (int kk = 0; kk < 32; kk += 16) {
            unsigned af[4][4], bf[4][2];
#pragma unroll
            for (int mt = 0; mt < 4; mt++) {
                unsigned addr = as_base + a_off + mt * 16 * (APH * 2) + kk * 2;
                ldsm4(af[mt][0], af[mt][1], af[mt][2], af[mt][3], addr);
            }
#pragma unroll
            for (int nt = 0; nt < 4; nt++) {
                if (!TRANSB) {
                    // ldmatrix.trans on [k][n] tile: rows kk+(lane&15), col n0w+nt*8
                    unsigned addr = bs_base + (kk + (lane & 15)) * (BPH_NN * 2)
                                  + (warp_n * 32 + nt * 8) * 2;
                    ldsm2t(bf[nt][0], bf[nt][1], addr);
                } else {
                    unsigned addr = bs_base + bnt_off + nt * 8 * (APH * 2) + kk * 2;
                    ldsm2(bf[nt][0], bf[nt][1], addr);
                }
            }
#pragma unroll
            for (int mt = 0; mt < 4; mt++)
#pragma unroll
                for (int nt = 0; nt < 4; nt++)
                    mma_f16(acc[mt * 4 + nt], af[mt][0], af[mt][1], af[mt][2], af[mt][3],
                            bf[nt][0], bf[nt][1]);
        }
        __syncthreads();
    }

    // ---- epilogue ----
#pragma unroll
    for (int mt = 0; mt < 4; mt++) {
#pragma unroll
        for (int nt = 0; nt < 4; nt++) {
            float* c = acc[mt * 4 + nt];
            int gm = m0 + warp_m * 64 + mt * 16 + qrow;
            int gn = n0 + warp_n * 32 + nt * 8 + (qcol << 1);
            float bx = 0.f, by = 0.f;
            if (bias && gn < N) { bx = bias[gn]; by = bias[gn + 1]; }
            if (OUTHALF) {
                __half* C = (__half*)Cv + blockIdx.z * sC;
                if (gm < M && gn < N) {
                    __half2 v = __floats2half2_rn(alpha * c[0] + bx, alpha * c[1] + by);
                    *(__half2*)(C + (long long)gm * ldc + gn) = v;
                }
                if (gm + 8 < M && gn < N) {
                    __half2 v = __floats2half2_rn(alpha * c[2] + bx, alpha * c[3] + by);
                    *(__half2*)(C + (long long)(gm + 8) * ldc + gn) = v;
                }
            } else {
                float* C = (float*)Cv + blockIdx.z * sC;
                if (gm < M && gn < N)
                    *(float2*)(C + (long long)gm * ldc + gn) =
                        make_float2(alpha * c[0] + bx, alpha * c[1] + by);
                if (gm + 8 < M && gn < N)
                    *(float2*)(C + (long long)(gm + 8) * ldc + gn) =
                        make_float2(alpha * c[2] + bx, alpha * c[3] + by);
            }
        }
    }
}

// ------------------- row softmax: fp32 scores -> half probs -------------------
__global__ __launch_bounds__(256) void softmax_rows_kernel(
    const float* __restrict__ S, __half* __restrict__ P, int Tk, int pitchS, int pitchP)
{
    long long row = blockIdx.x;
    const float* r = S + row * (long long)pitchS;
    __half* p = P + row * (long long)pitchP;
    int tid = threadIdx.x;
    __shared__ float red[256];

    float v[9];
    int cnt = 0;
    float mx = -1e30f;
    for (int i = tid; i < Tk; i += 256) {
        v[cnt] = r[i];
        mx = fmaxf(mx, v[cnt]);
        cnt++;
    }
    red[tid] = mx;
    __syncthreads();
    for (int s = 128; s > 0; s >>= 1) {
        if (tid < s) red[tid] = fmaxf(red[tid], red[tid + s]);
        __syncthreads();
    }
    mx = red[0];
    __syncthreads();

    float sum = 0.f;
    for (int c = 0; c < cnt; c++) {
        v[c] = __expf(v[c] - mx);
        sum += v[c];
    }
    red[tid] = sum;
    __syncthreads();
    for (int s = 128; s > 0; s >>= 1) {
        if (tid < s) red[tid] += red[tid + s];
        __syncthreads();
    }
    float inv = 1.f / red[0];

    cnt = 0;
    for (int i = tid; i < Tk; i += 256) p[i] = f2h(v[cnt++] * inv);
}

// ------------------- round/pack weights to fp16 -------------------
__global__ void pack_weights_kernel(const float* __restrict__ Wq, const float* __restrict__ Wk,
                                    const float* __restrict__ Wv, const float* __restrict__ Wo,
                                    const float* __restrict__ Wqm, const float* __restrict__ Wkm,
                                    const float* __restrict__ bq, const float* __restrict__ bk,
                                    const float* __restrict__ bv,
                                    __half* __restrict__ pack, __half* __restrict__ wo_h,
                                    __half* __restrict__ wqm_h, __half* __restrict__ wkm_h,
                                    float* __restrict__ bpack)
{
    int idx = blockIdx.x * blockDim.x + threadIdx.x;
    if (idx >= DD * DD) return;
    int k = idx >> 10, n = idx & (DD - 1);
    pack[k * ND3 + n] = f2h(Wq[idx]);
    pack[k * ND3 + DD + n] = f2h(Wk[idx]);
    pack[k * ND3 + 2 * DD + n] = f2h(Wv[idx]);
    wo_h[idx] = f2h(Wo[idx]);
    wqm_h[idx] = f2h(Wqm[idx]);
    wkm_h[idx] = f2h(Wkm[idx]);
    if (idx < DD) {
        bpack[idx] = bq[idx];
        bpack[DD + idx] = bk[idx];
        bpack[2 * DD + idx] = bv[idx];
    }
}

// ------------------- build inputs (fp16) -------------------
__global__ void build_x0_kernel(__half* __restrict__ X, const float* __restrict__ seg0)
{
    long long idx = (long long)blockIdx.x * blockDim.x + threadIdx.x;
    if (idx >= (long long)BB * T0V * DD) return;
    int d = (int)(idx & (DD - 1));
    long long r = idx >> 10;
    int t = (int)(r % T0V);
    int b = (int)(r / T0V);
    float v = 0.f;
    if (t >= 1 && t <= LL) v = seg0[((long long)b * LL + (t - 1)) * DD + d];
    X[idx] = f2h(v);
}

__global__ void build_xs_kernel(__half* __restrict__ X, const float* __restrict__ seg1,
                                const float* __restrict__ prompt)
{
    long long idx = (long long)blockIdx.x * blockDim.x + threadIdx.x;
    if (idx >= (long long)BB * TSV * DD) return;
    int d = (int)(idx & (DD - 1));
    long long r = idx >> 10;
    int t = (int)(r % TSV);
    int b = (int)(r / TSV);
    float v;
    if (t == 0 || t == TSV - 1) v = prompt[d];
    else v = seg1[((long long)b * LL + (t - 1)) * DD + d];
    X[idx] = f2h(v);
}

__global__ void build_x1_kernel(__half* __restrict__ X, const float* __restrict__ seg0,
                                const float* __restrict__ seg1, const float* __restrict__ P1)
{
    long long idx = (long long)blockIdx.x * blockDim.x + threadIdx.x;
    if (idx >= (long long)BB * T1V * DD) return;
    int d = (int)(idx & (DD - 1));
    long long r = idx >> 10;
    int t = (int)(r % T1V);
    int b = (int)(r / T1V);
    float v;
    if (t < KS) v = seg0[((long long)b * LL + (LL - KS + t)) * DD + d];
    else if (t == KS || t == T1V - 1) v = P1[b * DD + d];
    else v = seg1[((long long)b * LL + (t - KS - 1)) * DD + d];
    X[idx] = f2h(v);
}

__global__ void gather_q_kernel(__half* __restrict__ dst, const float* __restrict__ seg1)
{
    int idx = blockIdx.x * blockDim.x + threadIdx.x;
    if (idx >= BB * DD) return;
    int d = idx & (DD - 1);
    int b = idx >> 10;
    dst[idx] = f2h(seg1[((long long)b * LL + (JJ - 1)) * DD + d]);
}

__global__ void copy_rows_kernel(float* __restrict__ dst, const float* __restrict__ H,
                                 int T, int t_begin, int rows)
{
    long long idx = (long long)blockIdx.x * blockDim.x + threadIdx.x;
    if (idx >= (long long)BB * rows * DD) return;
    int d = (int)(idx & (DD - 1));
    long long r = idx >> 10;
    int t = (int)(r % rows);
    int b = (int)(r / rows);
    dst[idx] = H[((long long)b * T + t_begin + t) * DD + d];
}

// M1 row: keep fp32 and make half copy for the Kp GEMM
__global__ void copy_m1_kernel(float* __restrict__ m1, __half* __restrict__ m1h,
                               const float* __restrict__ H)
{
    int idx = blockIdx.x * blockDim.x + threadIdx.x;
    if (idx >= BB * DD) return;
    int d = idx & (DD - 1);
    int b = idx >> 10;
    float v = H[((long long)b * T0V + (T0V - 1)) * DD + d];
    m1[idx] = v;
    m1h[idx] = f2h(v);
}

// ------------------- summarize attention (half inputs, fp32 math) -------------------
__global__ __launch_bounds__(256) void summ_attn_kernel(
    const __half* __restrict__ Qrow, const __half* __restrict__ KV,
    __half* __restrict__ out, int T)
{
    int b = blockIdx.x;
    const __half* q = Qrow + b * DD;
    const __half* Kb = KV + (long long)b * T * 2048;
    int tid = threadIdx.x;
    int lane = tid & 31, warp = tid >> 5;
    __shared__ float sc[TSV];
    __shared__ float red[256];

    for (int j = warp; j < T; j += 8) {
        float s = 0.f;
        const __half* kr = Kb + (long long)j * 2048;
        for (int d = lane; d < DD; d += 32) s += __half2float(q[d]) * __half2float(kr[d]);
        for (int o = 16; o > 0; o >>= 1) s += __shfl_xor_sync(0xFFFFFFFFu, s, o);
        if (lane == 0) sc[j] = s * SCALE;
    }
    __syncthreads();

    float mx = -1e30f;
    for (int i = tid; i < T; i += 256) mx = fmaxf(mx, sc[i]);
    red[tid] = mx;
    __syncthreads();
    for (int s = 128; s > 0; s >>= 1) {
        if (tid < s) red[tid] = fmaxf(red[tid], red[tid + s]);
        __syncthreads();
    }
    mx = red[0];
    __syncthreads();

    float sum = 0.f;
    for (int i = tid; i < T; i += 256) {
        float e = __expf(sc[i] - mx);
        sc[i] = e;
        sum += e;
    }
    red[tid] = sum;
    __syncthreads();
    for (int s = 128; s > 0; s >>= 1) {
        if (tid < s) red[tid] += red[tid + s];
        __syncthreads();
    }
    float inv = 1.f / red[0];
    __syncthreads();
    for (int i = tid; i < T; i += 256) sc[i] *= inv;
    __syncthreads();

    const __half* Vb = Kb + DD;
    for (int d = tid; d < DD; d += 256) {
        float acc = 0.f;
        for (int j = 0; j < T; j++)
            acc = fmaf(sc[j], __half2float(Vb[(long long)j * 2048 + d]), acc);
        out[b * DD + d] = f2h(acc);
    }
}

// ------------------- memory attention (fp32) -------------------
__global__ __launch_bounds__(256) void mem_attn_kernel(
    const float* __restrict__ Qn, const float* __restrict__ Kp,
    const float* __restrict__ M1, float* __restrict__ P1)
{
    __shared__ float sc[BB][BB];
    int tid = threadIdx.x;
    int lane = tid & 31, warp = tid >> 5;

    for (int j = 0; j < BB; j++) {
        float s = 0.f;
        for (int d = lane; d < DD; d += 32) s += Qn[warp * DD + d] * Kp[j * DD + d];
        for (int o = 16; o > 0; o >>= 1) s += __shfl_xor_sync(0xFFFFFFFFu, s, o);
        if (lane == 0) sc[warp][j] = s * SCALE;
    }
    __syncthreads();

    if (tid < BB) {
        float mx = -1e30f;
        for (int j = 0; j < BB; j++) mx = fmaxf(mx, sc[tid][j]);
        float sum = 0.f;
        for (int j = 0; j < BB; j++) {
            float e = __expf(sc[tid][j] - mx);
            sc[tid][j] = e;
            sum += e;
        }
        float inv = 1.f / sum;
        for (int j = 0; j < BB; j++) sc[tid][j] *= inv;
    }
    __syncthreads();

    for (int idx = tid; idx < BB * DD; idx += 256) {
        int b = idx >> 10, d = idx & (DD - 1);
        float acc = 0.f;
        for (int j = 0; j < BB; j++) acc = fmaf(sc[b][j], M1[j * DD + d], acc);
        P1[idx] = acc;
    }
}

// ------------------- host orchestration -------------------
static inline void gemm(const __half* A, const __half* Bm, const float* bias, void* C,
                        int M, int N, int Kd, float alpha, int batch,
                        long long sA, long long sB, long long sC, bool transB,
                        int lda, int ldb, int ldc, bool outHalf)
{
    dim3 grid((N + 127) / 128, (M + 127) / 128, batch);
    if (transB) {
        if (outHalf) {
            cudaFuncSetAttribute(gemm_fp16_kernel<true, true>,
                                 cudaFuncAttributeMaxDynamicSharedMemorySize, GEMM_SMEM_BYTES);
            gemm_fp16_kernel<true, true><<<grid, 256, GEMM_SMEM_BYTES>>>(
                A, Bm, bias, C, M, N, Kd, alpha, lda, ldb, ldc, sA, sB, sC);
        } else {
            cudaFuncSetAttribute(gemm_fp16_kernel<true, false>,
                                 cudaFuncAttributeMaxDynamicSharedMemorySize, GEMM_SMEM_BYTES);
            gemm_fp16_kernel<true, false><<<grid, 256, GEMM_SMEM_BYTES>>>(
                A, Bm, bias, C, M, N, Kd, alpha, lda, ldb, ldc, sA, sB, sC);
        }
    } else {
        if (outHalf) {
            cudaFuncSetAttribute(gemm_fp16_kernel<false, true>,
                                 cudaFuncAttributeMaxDynamicSharedMemorySize, GEMM_SMEM_BYTES);
            gemm_fp16_kernel<false, true><<<grid, 256, GEMM_SMEM_BYTES>>>(
                A, Bm, bias, C, M, N, Kd, alpha, lda, ldb, ldc, sA, sB, sC);
        } else {
            cudaFuncSetAttribute(gemm_fp16_kernel<false, false>,
                                 cudaFuncAttributeMaxDynamicSharedMemorySize, GEMM_SMEM_BYTES);
            gemm_fp16_kernel<false, false><<<grid, 256, GEMM_SMEM_BYTES>>>(
                A, Bm, bias, C, M, N, Kd, alpha, lda, ldb, ldc, sA, sB, sC);
        }
    }
}

extern "C" void kernel_launch(void* const* d_in, const int* in_sizes, int n_in,
                              void* d_out, int out_size)
{
    const float* seg0   = (const float*)d_in[0];
    const float* seg1   = (const float*)d_in[1];
    const float* prompt = (const float*)d_in[2];
    const float* Wq_mem = (const float*)d_in[3];
    const float* bq_mem = (const float*)d_in[4];
    const float* Wk_mem = (const float*)d_in[5];
    const float* bk_mem = (const float*)d_in[6];
    const float* Wq     = (const float*)d_in[7];
    const float* bq     = (const float*)d_in[8];
    const float* Wk     = (const float*)d_in[9];
    const float* bk     = (const float*)d_in[10];
    const float* Wv     = (const float*)d_in[11];
    const float* bv     = (const float*)d_in[12];
    const float* Wo     = (const float*)d_in[13];
    const float* bo     = (const float*)d_in[14];
    float* out = (float*)d_out;

    __half *pXh, *pQKVh, *pPh, *pOh, *pWp, *pWoH, *pWqmH, *pWkmH;
    __half *pM1h, *pS1h, *pTAh, *pTBh;
    float *pS, *pH, *pbp, *pM1, *pQn, *pKp, *pP1;
    cudaGetSymbolAddress((void**)&pXh, g_Xh);
    cudaGetSymbolAddress((void**)&pQKVh, g_QKVh);
    cudaGetSymbolAddress((void**)&pPh, g_Ph);
    cudaGetSymbolAddress((void**)&pOh, g_Oh);
    cudaGetSymbolAddress((void**)&pS, g_S);
    cudaGetSymbolAddress((void**)&pH, g_H);
    cudaGetSymbolAddress((void**)&pWp, g_Wpack);
    cudaGetSymbolAddress((void**)&pWoH, g_Wo_h);
    cudaGetSymbolAddress((void**)&pWqmH, g_Wqm_h);
    cudaGetSymbolAddress((void**)&pWkmH, g_Wkm_h);
    cudaGetSymbolAddress((void**)&pbp, g_bpack);
    cudaGetSymbolAddress((void**)&pM1, g_M1);
    cudaGetSymbolAddress((void**)&pM1h, g_M1h);
    cudaGetSymbolAddress((void**)&pS1h, g_S1h);
    cudaGetSymbolAddress((void**)&pQn, g_Qn);
    cudaGetSymbolAddress((void**)&pKp, g_Kp);
    cudaGetSymbolAddress((void**)&pP1, g_P1);
    cudaGetSymbolAddress((void**)&pTAh, g_TAh);
    cudaGetSymbolAddress((void**)&pTBh, g_TBh);

    const int nthr = 256;

    pack_weights_kernel<<<(DD * DD + nthr - 1) / nthr, nthr>>>(
        Wq, Wk, Wv, Wo, Wq_mem, Wk_mem, bq, bk, bv, pWp, pWoH, pWqmH, pWkmH, pbp);

    // ---------------- Phase 0: backbone over [0, seg0, 0], T = 2050 ----------------
    {
        long long n = (long long)BB * T0V * DD;
        build_x0_kernel<<<(int)((n + nthr - 1) / nthr), nthr>>>(pXh, seg0);

        int M = BB * T0V;
        // fused QKV projection -> half (pitch 3072)
        gemm(pXh, pWp, pbp, pQKVh, M, ND3, DD, 1.f, 1, 0, 0, 0, false, DD, ND3, ND3, true);
        const __half* Qv = pQKVh;
        const __half* Kv = pQKVh + DD;
        const __half* Vv = pQKVh + 2 * DD;

        // scores (fp32 out)
        gemm(Qv, Kv, nullptr, pS, T0V, T0V, DD, SCALE, BB,
             (long long)T0V * ND3, (long long)T0V * ND3, (long long)T0V * SP0, true,
             ND3, ND3, SP0, false);
        softmax_rows_kernel<<<BB * T0V, 256>>>(pS, pPh, T0V, SP0, SPH0);
        // O = P @ V (half out)
        gemm(pPh, Vv, nullptr, pOh, T0V, DD, T0V, 1.f, BB,
             (long long)T0V * SPH0, (long long)T0V * ND3, (long long)T0V * DD, false,
             SPH0, ND3, DD, true);
        // H = O @ Wo + bo (fp32 out)
        gemm(pOh, pWoH, bo, pH, M, DD, DD, 1.f, 1, 0, 0, 0, false, DD, DD, DD, false);

        long long n0 = (long long)BB * OUT0_ROWS * DD;
        copy_rows_kernel<<<(int)((n0 + nthr - 1) / nthr), nthr>>>(out, pH, T0V, KS + 1, OUT0_ROWS);
        copy_m1_kernel<<<(BB * DD + nthr - 1) / nthr, nthr>>>(pM1, pM1h, pH);
    }

    // ---------------- Summarize(seg1): T = 514 ----------------
    {
        long long n = (long long)BB * TSV * DD;
        build_xs_kernel<<<(int)((n + nthr - 1) / nthr), nthr>>>(pXh, seg1, prompt);

        int M = BB * TSV;
        // fused K|V projection (N=2048), half out pitch 2048
        gemm(pXh, pWp + DD, pbp + DD, pQKVh, M, 2 * DD, DD, 1.f, 1, 0, 0, 0, false,
             DD, ND3, 2 * DD, true);

        gather_q_kernel<<<(BB * DD + nthr - 1) / nthr, nthr>>>(pTAh, seg1);
        gemm(pTAh, pWp, bq, pTBh, BB, DD, DD, 1.f, 1, 0, 0, 0, false, DD, ND3, DD, true);

        summ_attn_kernel<<<BB, 256>>>(pTBh, pQKVh, pTAh, TSV);
        gemm(pTAh, pWoH, bo, pS1h, BB, DD, DD, 1.f, 1, 0, 0, 0, false, DD, DD, DD, true);
    }

    // ---------------- Memory attention ----------------
    {
        gemm(pS1h, pWqmH, bq_mem, pQn, BB, DD, DD, 1.f, 1, 0, 0, 0, false, DD, DD, DD, false);
        gemm(pM1h, pWkmH, bk_mem, pKp, BB, DD, DD, 1.f, 1, 0, 0, 0, false, DD, DD, DD, false);
        mem_attn_kernel<<<1, 256>>>(pQn, pKp, pM1, pP1);
    }

    // ---------------- Phase 1: backbone over [sensory, P1, seg1, P1], T = 2082 ----------------
    {
        long long n = (long long)BB * T1V * DD;
        build_x1_kernel<<<(int)((n + nthr - 1) / nthr), nthr>>>(pXh, seg0, seg1, pP1);

        int M = BB * T1V;
        gemm(pXh, pWp, pbp, pQKVh, M, ND3, DD, 1.f, 1, 0, 0, 0, false, DD, ND3, ND3, true);
        const __half* Qv = pQKVh;
        const __half* Kv = pQKVh + DD;
        const __half* Vv = pQKVh + 2 * DD;

        gemm(Qv, Kv, nullptr, pS, T1V, T1V, DD, SCALE, BB,
             (long long)T1V * ND3, (long long)T1V * ND3, (long long)T1V * SP1, true,
             ND3, ND3, SP1, false);
        softmax_rows_kernel<<<BB * T1V, 256>>>(pS, pPh, T1V, SP1, SPH1);
        gemm(pPh, Vv, nullptr, pOh, T1V, DD, T1V, 1.f, BB,
             (long long)T1V * SPH1, (long long)T1V * ND3, (long long)T1V * DD, false,
             SPH1, ND3, DD, true);
        gemm(pOh, pWoH, bo, pH, M, DD, DD, 1.f, 1, 0, 0, 0, false, DD, DD, DD, false);

        long long n1 = (long long)BB * OUT1_ROWS * DD;
        copy_rows_kernel<<<(int)((n1 + nthr - 1) / nthr), nthr>>>(out + OFF1, pH, T1V, KS + 1, OUT1_ROWS);
    }
}